// round 1
// baseline (speedup 1.0000x reference)
#include <cuda_runtime.h>
#include <cuda_bf16.h>
#include <math.h>

// Problem constants
#define BB 128
#define TT 256
#define HH 768
#define KK 64

// Scratch: emissions [B*T, K] f32 = 8 MB
__device__ float g_emis[BB * TT * KK];

// ---------------------------------------------------------------------------
// Kernel 1: emissions = hidden @ W + b   (M=32768, N=64, K=768), f32
// BM=128, BN=64, BK=16, 256 threads, 8x4 register tile per thread
// ---------------------------------------------------------------------------
__global__ __launch_bounds__(256) void gemm_emis_kernel(
    const float* __restrict__ A,     // [32768, 768]
    const float* __restrict__ Wm,    // [768, 64]
    const float* __restrict__ bias)  // [64]
{
    __shared__ float As[16][132];   // transposed A tile, padded
    __shared__ float Bs[16][64];

    const int tid = threadIdx.x;
    const int m0 = blockIdx.x * 128;
    const int ty = tid >> 4;        // 0..15 -> rows ty*8..ty*8+7
    const int tx = tid & 15;        // 0..15 -> cols tx*4..tx*4+3

    float acc[8][4];
#pragma unroll
    for (int r = 0; r < 8; r++)
#pragma unroll
        for (int c = 0; c < 4; c++) acc[r][c] = 0.f;

    for (int kt = 0; kt < HH; kt += 16) {
        // Load A tile: 128x16 = 512 float4, 2 per thread
#pragma unroll
        for (int i = 0; i < 2; i++) {
            int s = tid + i * 256;
            int row = s >> 2;
            int c4 = s & 3;
            float4 v = *(const float4*)&A[(size_t)(m0 + row) * HH + kt + c4 * 4];
            As[c4 * 4 + 0][row] = v.x;
            As[c4 * 4 + 1][row] = v.y;
            As[c4 * 4 + 2][row] = v.z;
            As[c4 * 4 + 3][row] = v.w;
        }
        // Load B tile: 16x64 = 256 float4, 1 per thread
        {
            int row = tid >> 4;
            int c4 = tid & 15;
            *(float4*)&Bs[row][c4 * 4] = *(const float4*)&Wm[(size_t)(kt + row) * KK + c4 * 4];
        }
        __syncthreads();

#pragma unroll
        for (int kk = 0; kk < 16; kk++) {
            float4 a0 = *(const float4*)&As[kk][ty * 8];
            float4 a1 = *(const float4*)&As[kk][ty * 8 + 4];
            float4 bv = *(const float4*)&Bs[kk][tx * 4];
            float a[8] = {a0.x, a0.y, a0.z, a0.w, a1.x, a1.y, a1.z, a1.w};
#pragma unroll
            for (int r = 0; r < 8; r++) {
                acc[r][0] += a[r] * bv.x;
                acc[r][1] += a[r] * bv.y;
                acc[r][2] += a[r] * bv.z;
                acc[r][3] += a[r] * bv.w;
            }
        }
        __syncthreads();
    }

    float4 bb = *(const float4*)&bias[tx * 4];
#pragma unroll
    for (int r = 0; r < 8; r++) {
        float4 o;
        o.x = acc[r][0] + bb.x;
        o.y = acc[r][1] + bb.y;
        o.z = acc[r][2] + bb.z;
        o.w = acc[r][3] + bb.w;
        *(float4*)&g_emis[(size_t)(m0 + ty * 8 + r) * KK + tx * 4] = o;
    }
}

// ---------------------------------------------------------------------------
// Kernel 2: per-batch CRF forward (log-norm) + Viterbi + decode + seq_score
// One block per batch. 256 threads:
//   tid 0..127  : log-sum-exp recurrence (2 threads per output state)
//   tid 128..255: Viterbi max/argmax     (2 threads per output state)
// Trick: logsumexp_k(alpha_k + T_kj) = M + log( sum_k exp(alpha_k - M) * E_kj )
// with E = exp(trans) precomputed once. trans in [0,1) => alpha spread bounded,
// so M = alpha[0] is numerically sufficient (no max reduction per step).
// ---------------------------------------------------------------------------
__global__ __launch_bounds__(256) void crf_kernel(
    const int* __restrict__ masks,     // [B, T]
    const int* __restrict__ target,    // [B, T]
    const float* __restrict__ trans_g, // [K, K]
    float* __restrict__ out_dec,       // [B, T] (as float)
    float* __restrict__ out_ll)        // [B]
{
    extern __shared__ float smem_f[];
    float* s_trans = smem_f;                 // 4096
    float* s_E     = smem_f + 4096;          // 4096
    float* s_alpha = smem_f + 8192;          // 64
    float* s_v     = s_alpha + 64;           // 64
    float* s_p     = s_v + 64;               // 64
    float* s_e     = s_p + 64;               // 64
    float* s_red   = s_e + 64;               // 64
    int*   s_path  = (int*)(s_red + 64);     // 256
    unsigned char* s_bp = (unsigned char*)(s_path + 256); // 255*64

    const int b = blockIdx.x;
    const int tid = threadIdx.x;
    const int lane = tid & 31;
    const int wrp = tid >> 5;

    // Load transition matrix + its exp
    for (int i = tid; i < 4096; i += 256) {
        float tv = trans_g[i];
        s_trans[i] = tv;
        s_E[i] = expf(tv);
    }

    // seq_len = sum(masks[b,:])
    int mv = masks[b * TT + tid];
#pragma unroll
    for (int o = 16; o; o >>= 1) mv += __shfl_xor_sync(0xFFFFFFFFu, mv, o);
    int* s_ri = (int*)s_red;
    if (lane == 0) s_ri[wrp] = mv;
    __syncthreads();
    int len = 0;
#pragma unroll
    for (int w = 0; w < 8; w++) len += s_ri[w];
    __syncthreads();

    // Init alpha = v = emissions[b, 0, :]
    if (tid < 64) {
        float e0 = g_emis[((size_t)b * TT + 0) * KK + tid];
        s_alpha[tid] = e0;
        s_v[tid] = e0;
    }
    __syncthreads();

    const bool roleA = (tid < 128);
    const int j = (tid & 127) >> 1;   // output state 0..63
    const int half = tid & 1;
    const int k0 = half * 32;

    for (int t = 1; t < TT; t++) {
        // Phase 1: stage p[k] = exp(alpha[k]-M) and emissions row
        if (tid < 64) {
            float M0 = s_alpha[0];
            s_p[tid] = expf(s_alpha[tid] - M0);
            s_e[tid] = g_emis[((size_t)b * TT + t) * KK + tid];
        }
        __syncthreads();

        float M = s_alpha[0];
        float part_s = 0.f;
        float bv = -1e30f;
        int ba = 0;

        if (roleA) {
#pragma unroll
            for (int kk = 0; kk < 32; kk++) {
                int k = k0 + kk;
                part_s += s_p[k] * s_E[k * KK + j];
            }
            part_s += __shfl_xor_sync(0xFFFFFFFFu, part_s, 1);
        } else {
#pragma unroll
            for (int kk = 0; kk < 32; kk++) {
                int k = k0 + kk;
                float sc = s_v[k] + s_trans[k * KK + j];
                if (sc > bv) { bv = sc; ba = k; }
            }
            float ov = __shfl_xor_sync(0xFFFFFFFFu, bv, 1);
            int   oa = __shfl_xor_sync(0xFFFFFFFFu, ba, 1);
            // half0 holds k<32: strict > keeps lower-k on tie (matches argmax)
            if (ov > bv) { bv = ov; ba = oa; }
        }

        float newalpha = 0.f, newv = 0.f;
        int bpv = 0;
        if (half == 0) {
            float e = s_e[j];
            if (roleA) {
                newalpha = (t < len) ? (M + logf(part_s) + e) : s_alpha[j];
            } else {
                if (t < len) { newv = bv + e; bpv = ba; }
                else         { newv = s_v[j]; bpv = j; }
            }
        }
        __syncthreads();
        if (half == 0) {
            if (roleA) s_alpha[j] = newalpha;
            else { s_v[j] = newv; s_bp[(t - 1) * KK + j] = (unsigned char)bpv; }
        }
        __syncthreads();
    }

    // seq_score partial (one t per thread)
    int tgt = target[b * TT + tid];
    float uacc = 0.f;
    if (tid < len) uacc = g_emis[((size_t)b * TT + tid) * KK + tgt];
    if (tid >= 1 && tid < len) {
        int tp = target[b * TT + tid - 1];
        uacc += s_trans[tp * KK + tgt];
    }
#pragma unroll
    for (int o = 16; o; o >>= 1) uacc += __shfl_xor_sync(0xFFFFFFFFu, uacc, o);
    if (lane == 0) s_red[wrp] = uacc;
    __syncthreads();

    if (tid == 0) {
        float score = 0.f;
#pragma unroll
        for (int w = 0; w < 8; w++) score += s_red[w];
        // log_norm = logsumexp(final alpha)
        float M2 = s_alpha[0];
#pragma unroll
        for (int k = 1; k < KK; k++) M2 = fmaxf(M2, s_alpha[k]);
        float ss = 0.f;
#pragma unroll
        for (int k = 0; k < KK; k++) ss += expf(s_alpha[k] - M2);
        out_ll[b] = score - (M2 + logf(ss));

        // Viterbi backtrack (first-max tie-break like jnp.argmax)
        float bvv = s_v[0];
        int tg = 0;
#pragma unroll
        for (int k = 1; k < KK; k++) {
            if (s_v[k] > bvv) { bvv = s_v[k]; tg = k; }
        }
        s_path[TT - 1] = tg;
        for (int t = TT - 1; t >= 1; t--) {
            tg = s_bp[(t - 1) * KK + tg];
            s_path[t - 1] = tg;
        }
    }
    __syncthreads();

    out_dec[(size_t)b * TT + tid] = (float)((tid < len) ? s_path[tid] : 0);
}

// ---------------------------------------------------------------------------
extern "C" void kernel_launch(void* const* d_in, const int* in_sizes, int n_in,
                              void* d_out, int out_size) {
    const float* hidden = (const float*)d_in[0];   // [128,256,768]
    const int*   masks  = (const int*)d_in[1];     // [128,256]
    const int*   target = (const int*)d_in[2];     // [128,256]
    const float* Wm     = (const float*)d_in[3];   // [768,64]
    const float* bias   = (const float*)d_in[4];   // [64]
    const float* trans  = (const float*)d_in[5];   // [64,64]
    float* out = (float*)d_out;                    // [128*256 decode | 128 ll]

    gemm_emis_kernel<<<BB * TT / 128, 256>>>(hidden, Wm, bias);

    const size_t SMEM = (4096 + 4096 + 64 * 5) * sizeof(float)
                      + 256 * sizeof(int) + 255 * 64;  // 51392 B
    cudaFuncSetAttribute(crf_kernel, cudaFuncAttributeMaxDynamicSharedMemorySize,
                         (int)SMEM);
    crf_kernel<<<BB, 256, SMEM>>>(masks, target, trans, out, out + (size_t)BB * TT);
}

// round 2
// speedup vs baseline: 1.6411x; 1.6411x over previous
#include <cuda_runtime.h>
#include <cuda_bf16.h>
#include <math.h>

#define BB 128
#define TT 256
#define HH 768
#define KK 64

typedef unsigned long long u64t;

__device__ float g_emis[BB * TT * KK];   // emissions scratch, 8 MB

// ---- packed f32x2 helpers ------------------------------------------------
__device__ __forceinline__ u64t ffma2(u64t a, u64t b, u64t c) {
    u64t d;
    asm("fma.rn.f32x2 %0, %1, %2, %3;" : "=l"(d) : "l"(a), "l"(b), "l"(c));
    return d;
}
__device__ __forceinline__ u64t pack2(float lo, float hi) {
    u64t d;
    unsigned a = __float_as_uint(lo), b = __float_as_uint(hi);
    asm("mov.b64 %0, {%1, %2};" : "=l"(d) : "r"(a), "r"(b));
    return d;
}
__device__ __forceinline__ void unpack2(u64t v, float* lo, float* hi) {
    unsigned a, b;
    asm("mov.b64 {%0, %1}, %2;" : "=r"(a), "=r"(b) : "l"(v));
    *lo = __uint_as_float(a);
    *hi = __uint_as_float(b);
}

// ---------------------------------------------------------------------------
// Kernel 1: emissions = hidden @ W + b   (M=32768, N=64, K=768), f32
// BM=128, BN=64, BK=16, 256 threads, 8x4 thread tile, f32x2 packed FMA,
// gmem->reg prefetch overlapping compute.
// ---------------------------------------------------------------------------
__global__ __launch_bounds__(256) void gemm_emis_kernel(
    const float* __restrict__ A,
    const float* __restrict__ Wm,
    const float* __restrict__ bias)
{
    __shared__ float As[16][132];   // transposed A tile (row stride 132 floats, 8B-aligned)
    __shared__ float Bs[16][64];

    const int tid = threadIdx.x;
    const int m0 = blockIdx.x * 128;
    const int ty = tid >> 4;
    const int tx = tid & 15;

    // accumulators: row pairs (2rp, 2rp+1) x 4 cols, packed f32x2 over rows
    u64t acc2[4][4];
#pragma unroll
    for (int rp = 0; rp < 4; rp++)
#pragma unroll
        for (int c = 0; c < 4; c++) acc2[rp][c] = 0ull;

    const int arow0 = (tid) >> 2,      ac40 = (tid) & 3;
    const int arow1 = (tid + 256) >> 2, ac41 = (tid + 256) & 3;
    const int brow = tid >> 4, bc4 = tid & 15;

    // prefetch tile 0
    float4 aReg0 = *(const float4*)&A[(size_t)(m0 + arow0) * HH + ac40 * 4];
    float4 aReg1 = *(const float4*)&A[(size_t)(m0 + arow1) * HH + ac41 * 4];
    float4 bReg  = *(const float4*)&Wm[(size_t)(brow) * KK + bc4 * 4];

    for (int kt = 0; kt < HH; kt += 16) {
        // store staged tile
        As[ac40 * 4 + 0][arow0] = aReg0.x;
        As[ac40 * 4 + 1][arow0] = aReg0.y;
        As[ac40 * 4 + 2][arow0] = aReg0.z;
        As[ac40 * 4 + 3][arow0] = aReg0.w;
        As[ac41 * 4 + 0][arow1] = aReg1.x;
        As[ac41 * 4 + 1][arow1] = aReg1.y;
        As[ac41 * 4 + 2][arow1] = aReg1.z;
        As[ac41 * 4 + 3][arow1] = aReg1.w;
        *(float4*)&Bs[brow][bc4 * 4] = bReg;
        __syncthreads();

        // prefetch next tile (overlaps compute)
        if (kt + 16 < HH) {
            aReg0 = *(const float4*)&A[(size_t)(m0 + arow0) * HH + kt + 16 + ac40 * 4];
            aReg1 = *(const float4*)&A[(size_t)(m0 + arow1) * HH + kt + 16 + ac41 * 4];
            bReg  = *(const float4*)&Wm[(size_t)(kt + 16 + brow) * KK + bc4 * 4];
        }

#pragma unroll
        for (int kk = 0; kk < 16; kk++) {
            const u64t* ap = (const u64t*)&As[kk][ty * 8];
            u64t a2[4];
#pragma unroll
            for (int rp = 0; rp < 4; rp++) a2[rp] = ap[rp];
            float4 bv = *(const float4*)&Bs[kk][tx * 4];
            u64t bd[4];
            bd[0] = pack2(bv.x, bv.x);
            bd[1] = pack2(bv.y, bv.y);
            bd[2] = pack2(bv.z, bv.z);
            bd[3] = pack2(bv.w, bv.w);
#pragma unroll
            for (int rp = 0; rp < 4; rp++)
#pragma unroll
                for (int c = 0; c < 4; c++)
                    acc2[rp][c] = ffma2(a2[rp], bd[c], acc2[rp][c]);
        }
        __syncthreads();
    }

    float4 bb = *(const float4*)&bias[tx * 4];
    const float bbv[4] = {bb.x, bb.y, bb.z, bb.w};
#pragma unroll
    for (int rp = 0; rp < 4; rp++) {
        float o0[4], o1[4];
#pragma unroll
        for (int c = 0; c < 4; c++) {
            float lo, hi;
            unpack2(acc2[rp][c], &lo, &hi);
            o0[c] = lo + bbv[c];
            o1[c] = hi + bbv[c];
        }
        int row = m0 + ty * 8 + 2 * rp;
        *(float4*)&g_emis[(size_t)row * KK + tx * 4]       = make_float4(o0[0], o0[1], o0[2], o0[3]);
        *(float4*)&g_emis[(size_t)(row + 1) * KK + tx * 4] = make_float4(o1[0], o1[1], o1[2], o1[3]);
    }
}

// ---------------------------------------------------------------------------
// Kernel 2: CRF forward + Viterbi, one block (192 threads) per batch.
//   tid 0..63   roleA: log-norm recurrence, one state j per thread,
//               E[:,j]=exp(trans[:,j]) in 32 packed f32x2 registers.
//               Unnormalized rep: alpha_j = A + log P_j,
//               P'_j = (sum_k P_k E_kj / P_0) * exp(e_j),  A += log P_0.
//   tid 64..191 roleB: Viterbi, 2 threads per state (32 prev-states each),
//               trans column in 32 registers, shfl combine.
// Single __syncthreads per step via double-buffered s_P/s_v.
// ---------------------------------------------------------------------------
__global__ __launch_bounds__(192) void crf_kernel(
    const int* __restrict__ masks,
    const int* __restrict__ target,
    const float* __restrict__ trans_g,
    float* __restrict__ out_dec,
    float* __restrict__ out_ll)
{
    __shared__ float s_P[2][64];
    __shared__ float s_v[2][64];
    __shared__ float s_red[8];
    __shared__ int s_len;
    __shared__ int s_path[TT];
    __shared__ unsigned char s_bp[(TT - 1) * KK];

    const int b = blockIdx.x;
    const int tid = threadIdx.x;

    // seq_len
    if (tid < 32) {
        int acc = 0;
        for (int i = tid; i < TT; i += 32) acc += masks[b * TT + i];
#pragma unroll
        for (int o = 16; o; o >>= 1) acc += __shfl_xor_sync(0xFFFFFFFFu, acc, o);
        if (tid == 0) s_len = acc;
    }

    const bool isA = (tid < 64);
    const int j = isA ? tid : ((tid - 64) >> 1);
    const int h = (tid - 64) & 1;
    const int k0 = h * 32;

    // register-resident matrix columns
    u64t E2[32];
    float Tcol[32];
    if (isA) {
#pragma unroll
        for (int m = 0; m < 32; m++) {
            float t0 = trans_g[(2 * m) * KK + j];
            float t1 = trans_g[(2 * m + 1) * KK + j];
            E2[m] = pack2(expf(t0), expf(t1));
        }
    } else {
#pragma unroll
        for (int kk = 0; kk < 32; kk++)
            Tcol[kk] = trans_g[(k0 + kk) * KK + j];
    }

    // init (t = 0)
    const float* emisb = &g_emis[(size_t)b * TT * KK];
    float e0 = emisb[j];
    float e_cur = emisb[KK + j];   // prefetch t=1
    float prevP = 0.f, prevV = 0.f, Aoff = 0.f;
    if (isA) {
        prevP = expf(e0);
        s_P[0][j] = prevP;
    } else if (h == 0) {
        prevV = e0;
        s_v[0][j] = e0;
    }
    __syncthreads();
    const int len = s_len;
    int buf = 0;

    for (int t = 1; t < TT; t++) {
        float e_next = (t < TT - 1) ? emisb[(size_t)(t + 1) * KK + j] : 0.f;

        if (isA) {
            float p0 = s_P[buf][0];
            const u64t* P2 = (const u64t*)&s_P[buf][0];
            u64t s2a = 0ull, s2b = 0ull;
#pragma unroll
            for (int m = 0; m < 16; m++) {
                s2a = ffma2(P2[2 * m],     E2[2 * m],     s2a);
                s2b = ffma2(P2[2 * m + 1], E2[2 * m + 1], s2b);
            }
            float la, ha, lb, hb;
            unpack2(s2a, &la, &ha);
            unpack2(s2b, &lb, &hb);
            float S = (la + ha) + (lb + hb);
            if (t < len) {
                prevP = S * (1.0f / p0) * expf(e_cur);
                Aoff += logf(p0);
            }
            s_P[buf ^ 1][j] = prevP;
        } else {
            const float4* V4 = (const float4*)&s_v[buf][k0];
            float bv = -1e30f;
            int ba = 0;
#pragma unroll
            for (int q = 0; q < 8; q++) {
                float4 v4 = V4[q];
                float sc;
                sc = v4.x + Tcol[4 * q + 0]; if (sc > bv) { bv = sc; ba = k0 + 4 * q + 0; }
                sc = v4.y + Tcol[4 * q + 1]; if (sc > bv) { bv = sc; ba = k0 + 4 * q + 1; }
                sc = v4.z + Tcol[4 * q + 2]; if (sc > bv) { bv = sc; ba = k0 + 4 * q + 2; }
                sc = v4.w + Tcol[4 * q + 3]; if (sc > bv) { bv = sc; ba = k0 + 4 * q + 3; }
            }
            float ov = __shfl_xor_sync(0xFFFFFFFFu, bv, 1);
            int   oa = __shfl_xor_sync(0xFFFFFFFFu, ba, 1);
            // for h==0 the partner holds k>=32: strictly-greater keeps lower k on tie
            if (ov > bv) { bv = ov; ba = oa; }
            if (h == 0) {
                int bp;
                if (t < len) { prevV = bv + e_cur; bp = ba; }
                else         { bp = j; }
                s_v[buf ^ 1][j] = prevV;
                s_bp[(t - 1) * KK + j] = (unsigned char)bp;
            }
        }
        e_cur = e_next;
        __syncthreads();
        buf ^= 1;
    }

    // log_norm partial: sum of final P over roleA warps
    if (isA) {
        float sp = prevP;
#pragma unroll
        for (int o = 16; o; o >>= 1) sp += __shfl_xor_sync(0xFFFFFFFFu, sp, o);
        if ((tid & 31) == 0) s_red[tid >> 5] = sp;
    }
    __syncthreads();

    // seq_score partials
    float uacc = 0.f;
    for (int tt = tid; tt < TT; tt += 192) {
        if (tt < len) {
            int tg = target[b * TT + tt];
            uacc += emisb[(size_t)tt * KK + tg];
            if (tt >= 1) uacc += trans_g[target[b * TT + tt - 1] * KK + tg];
        }
    }
#pragma unroll
    for (int o = 16; o; o >>= 1) uacc += __shfl_xor_sync(0xFFFFFFFFu, uacc, o);
    if ((tid & 31) == 0) s_red[2 + (tid >> 5)] = uacc;
    __syncthreads();

    if (tid == 0) {
        float sumP = s_red[0] + s_red[1];
        float score = 0.f;
#pragma unroll
        for (int w = 0; w < 6; w++) score += s_red[2 + w];
        out_ll[b] = score - (Aoff + logf(sumP));

        // Viterbi backtrack
        float bvv = s_v[buf][0];
        int tg = 0;
#pragma unroll
        for (int k = 1; k < KK; k++)
            if (s_v[buf][k] > bvv) { bvv = s_v[buf][k]; tg = k; }
        s_path[TT - 1] = tg;
        for (int t = TT - 1; t >= 1; t--) {
            tg = s_bp[(t - 1) * KK + tg];
            s_path[t - 1] = tg;
        }
    }
    __syncthreads();

    for (int tt = tid; tt < TT; tt += 192)
        out_dec[(size_t)b * TT + tt] = (float)((tt < len) ? s_path[tt] : 0);
}

// ---------------------------------------------------------------------------
extern "C" void kernel_launch(void* const* d_in, const int* in_sizes, int n_in,
                              void* d_out, int out_size) {
    const float* hidden = (const float*)d_in[0];
    const int*   masks  = (const int*)d_in[1];
    const int*   target = (const int*)d_in[2];
    const float* Wm     = (const float*)d_in[3];
    const float* bias   = (const float*)d_in[4];
    const float* trans  = (const float*)d_in[5];
    float* out = (float*)d_out;

    gemm_emis_kernel<<<BB * TT / 128, 256>>>(hidden, Wm, bias);
    crf_kernel<<<BB, 192>>>(masks, target, trans, out, out + (size_t)BB * TT);
}

// round 3
// speedup vs baseline: 1.7861x; 1.0884x over previous
#include <cuda_runtime.h>
#include <cuda_bf16.h>
#include <math.h>

#define BB 128
#define TT 256
#define HH 768
#define KK 64

typedef unsigned long long u64t;

__device__ float g_emis[BB * TT * KK];   // emissions scratch, 8 MB

// ---- packed f32x2 helpers ------------------------------------------------
__device__ __forceinline__ u64t ffma2(u64t a, u64t b, u64t c) {
    u64t d;
    asm("fma.rn.f32x2 %0, %1, %2, %3;" : "=l"(d) : "l"(a), "l"(b), "l"(c));
    return d;
}
__device__ __forceinline__ u64t pack2(float lo, float hi) {
    u64t d;
    unsigned a = __float_as_uint(lo), b = __float_as_uint(hi);
    asm("mov.b64 %0, {%1, %2};" : "=l"(d) : "r"(a), "r"(b));
    return d;
}
__device__ __forceinline__ void unpack2(u64t v, float* lo, float* hi) {
    unsigned a, b;
    asm("mov.b64 {%0, %1}, %2;" : "=r"(a), "=r"(b) : "l"(v));
    *lo = __uint_as_float(a);
    *hi = __uint_as_float(b);
}

// ---------------------------------------------------------------------------
// Kernel 1: emissions = hidden @ W + b (unchanged from round 2)
// ---------------------------------------------------------------------------
__global__ __launch_bounds__(256) void gemm_emis_kernel(
    const float* __restrict__ A,
    const float* __restrict__ Wm,
    const float* __restrict__ bias)
{
    __shared__ float As[16][132];
    __shared__ float Bs[16][64];

    const int tid = threadIdx.x;
    const int m0 = blockIdx.x * 128;
    const int ty = tid >> 4;
    const int tx = tid & 15;

    u64t acc2[4][4];
#pragma unroll
    for (int rp = 0; rp < 4; rp++)
#pragma unroll
        for (int c = 0; c < 4; c++) acc2[rp][c] = 0ull;

    const int arow0 = (tid) >> 2,       ac40 = (tid) & 3;
    const int arow1 = (tid + 256) >> 2, ac41 = (tid + 256) & 3;
    const int brow = tid >> 4, bc4 = tid & 15;

    float4 aReg0 = *(const float4*)&A[(size_t)(m0 + arow0) * HH + ac40 * 4];
    float4 aReg1 = *(const float4*)&A[(size_t)(m0 + arow1) * HH + ac41 * 4];
    float4 bReg  = *(const float4*)&Wm[(size_t)(brow) * KK + bc4 * 4];

    for (int kt = 0; kt < HH; kt += 16) {
        As[ac40 * 4 + 0][arow0] = aReg0.x;
        As[ac40 * 4 + 1][arow0] = aReg0.y;
        As[ac40 * 4 + 2][arow0] = aReg0.z;
        As[ac40 * 4 + 3][arow0] = aReg0.w;
        As[ac41 * 4 + 0][arow1] = aReg1.x;
        As[ac41 * 4 + 1][arow1] = aReg1.y;
        As[ac41 * 4 + 2][arow1] = aReg1.z;
        As[ac41 * 4 + 3][arow1] = aReg1.w;
        *(float4*)&Bs[brow][bc4 * 4] = bReg;
        __syncthreads();

        if (kt + 16 < HH) {
            aReg0 = *(const float4*)&A[(size_t)(m0 + arow0) * HH + kt + 16 + ac40 * 4];
            aReg1 = *(const float4*)&A[(size_t)(m0 + arow1) * HH + kt + 16 + ac41 * 4];
            bReg  = *(const float4*)&Wm[(size_t)(kt + 16 + brow) * KK + bc4 * 4];
        }

#pragma unroll
        for (int kk = 0; kk < 16; kk++) {
            const u64t* ap = (const u64t*)&As[kk][ty * 8];
            u64t a2[4];
#pragma unroll
            for (int rp = 0; rp < 4; rp++) a2[rp] = ap[rp];
            float4 bv = *(const float4*)&Bs[kk][tx * 4];
            u64t bd[4];
            bd[0] = pack2(bv.x, bv.x);
            bd[1] = pack2(bv.y, bv.y);
            bd[2] = pack2(bv.z, bv.z);
            bd[3] = pack2(bv.w, bv.w);
#pragma unroll
            for (int rp = 0; rp < 4; rp++)
#pragma unroll
                for (int c = 0; c < 4; c++)
                    acc2[rp][c] = ffma2(a2[rp], bd[c], acc2[rp][c]);
        }
        __syncthreads();
    }

    float4 bb = *(const float4*)&bias[tx * 4];
    const float bbv[4] = {bb.x, bb.y, bb.z, bb.w};
#pragma unroll
    for (int rp = 0; rp < 4; rp++) {
        float o0[4], o1[4];
#pragma unroll
        for (int c = 0; c < 4; c++) {
            float lo, hi;
            unpack2(acc2[rp][c], &lo, &hi);
            o0[c] = lo + bbv[c];
            o1[c] = hi + bbv[c];
        }
        int row = m0 + ty * 8 + 2 * rp;
        *(float4*)&g_emis[(size_t)row * KK + tx * 4]       = make_float4(o0[0], o0[1], o0[2], o0[3]);
        *(float4*)&g_emis[(size_t)(row + 1) * KK + tx * 4] = make_float4(o1[0], o1[1], o1[2], o1[3]);
    }
}

// ---------------------------------------------------------------------------
// Kernel 2: CRF forward + Viterbi. 192 threads per block, one block per batch.
//   tid 0..63   (fwd): one state each. Unnormalized P with EXACT power-of-2
//               rescaling (integer exponent accumulator; no logf, no div in
//               the loop). P'_j = (sum_k P_k E_kj) * 2^{-exp(p0)} * __expf(e_j)
//   tid 64..191 (vit): 2 threads/state, 32 candidates each; pairwise + tree
//               max/argmax (depth ~5), exact first-max tie-break; shfl combine.
// One __syncthreads per step (double-buffered s_P / s_v).
// ---------------------------------------------------------------------------
__global__ __launch_bounds__(192) void crf_kernel(
    const int* __restrict__ masks,
    const int* __restrict__ target,
    const float* __restrict__ trans_g,
    float* __restrict__ out_dec,
    float* __restrict__ out_ll)
{
    __shared__ __align__(16) float s_P[2][64];
    __shared__ __align__(16) float s_v[2][64];
    __shared__ float s_red[8];
    __shared__ int s_len;
    __shared__ int s_path[TT];
    __shared__ unsigned char s_bp[(TT - 1) * KK];

    const int b = blockIdx.x;
    const int tid = threadIdx.x;

    // seq_len
    if (tid < 32) {
        int acc = 0;
        for (int i = tid; i < TT; i += 32) acc += masks[b * TT + i];
#pragma unroll
        for (int o = 16; o; o >>= 1) acc += __shfl_xor_sync(0xFFFFFFFFu, acc, o);
        if (tid == 0) s_len = acc;
    }

    const bool isA = (tid < 64);
    const int j = isA ? tid : ((tid - 64) >> 1);
    const int h = isA ? 0 : ((tid - 64) & 1);
    const int k0 = h * 32;

    // register-resident matrix columns
    u64t E2[32];     // fwd: full exp(trans) column, packed pairs
    float Tcol[32];  // vit: half of trans column
    if (isA) {
#pragma unroll
        for (int m = 0; m < 32; m++) {
            float t0 = trans_g[(2 * m) * KK + j];
            float t1 = trans_g[(2 * m + 1) * KK + j];
            E2[m] = pack2(expf(t0), expf(t1));
        }
    } else {
#pragma unroll
        for (int kk = 0; kk < 32; kk++)
            Tcol[kk] = trans_g[(k0 + kk) * KK + j];
    }

    // init t=0; prefetch emissions for t=1, t=2 (distance-2 pipeline)
    const float* emisb = &g_emis[(size_t)b * TT * KK];
    float e0 = emisb[j];
    float eA = emisb[KK + j];
    float eB = emisb[2 * KK + j];
    float prevP = 0.f, prevV = 0.f;
    int iexp = 0;
    if (isA) {
        prevP = __expf(e0);
        s_P[0][j] = prevP;
    } else if (h == 0) {
        prevV = e0;
        s_v[0][j] = e0;
    }
    __syncthreads();
    const int len = s_len;
    int buf = 0;

    for (int t = 1; t < TT; t++) {
        float eC = (t + 2 < TT) ? emisb[(size_t)(t + 2) * KK + j] : 0.f;

        if (isA) {
            // ---- forward: S_j = sum_k P_k * E_kj (two interleaved FFMA2 chains)
            float p0 = s_P[buf][0];
            const float4* P4 = (const float4*)&s_P[buf][0];
            u64t s2a = 0ull, s2b = 0ull;
#pragma unroll
            for (int q = 0; q < 16; q++) {
                float4 p = P4[q];
                s2a = ffma2(pack2(p.x, p.y), E2[2 * q],     s2a);
                s2b = ffma2(pack2(p.z, p.w), E2[2 * q + 1], s2b);
            }
            float la, ha, lb, hb;
            unpack2(s2a, &la, &ha);
            unpack2(s2b, &lb, &hb);
            float S = (la + ha) + (lb + hb);
            // exact power-of-2 rescale by p0's exponent (no div, no logf)
            int e0i = (int)(__float_as_uint(p0) >> 23);
            float scale = __uint_as_float((unsigned)(254 - e0i) << 23);
            if (t < len) {
                prevP = S * scale * __expf(eA);
                iexp += e0i - 127;
            }
            s_P[buf ^ 1][j] = prevP;
        } else {
            // ---- viterbi: pairwise + tree max/argmax, first-max tie-break
            const float4* V4 = (const float4*)&s_v[buf][k0];
            float pv[16];
            int   pi[16];
#pragma unroll
            for (int q = 0; q < 8; q++) {
                float4 v4 = V4[q];
                float a0 = v4.x + Tcol[4 * q + 0];
                float a1 = v4.y + Tcol[4 * q + 1];
                float a2 = v4.z + Tcol[4 * q + 2];
                float a3 = v4.w + Tcol[4 * q + 3];
                bool g1 = a1 > a0;
                pv[2 * q]     = g1 ? a1 : a0;
                pi[2 * q]     = g1 ? 4 * q + 1 : 4 * q + 0;
                bool g3 = a3 > a2;
                pv[2 * q + 1] = g3 ? a3 : a2;
                pi[2 * q + 1] = g3 ? 4 * q + 3 : 4 * q + 2;
            }
#pragma unroll
            for (int s = 1; s < 16; s <<= 1) {
#pragma unroll
                for (int m = 0; m < 16; m += 2 * s) {
                    bool g = pv[m + s] > pv[m];   // strict: lower index wins ties
                    pv[m] = g ? pv[m + s] : pv[m];
                    pi[m] = g ? pi[m + s] : pi[m];
                }
            }
            float bv = pv[0];
            int   ba = k0 + pi[0];
            float ov = __shfl_xor_sync(0xFFFFFFFFu, bv, 1);
            int   oa = __shfl_xor_sync(0xFFFFFFFFu, ba, 1);
            if (ov > bv) { bv = ov; ba = oa; }   // h0 keeps k<32 on tie
            if (h == 0) {
                int bp;
                if (t < len) { prevV = bv + eA; bp = ba; }
                else         { bp = j; }
                s_v[buf ^ 1][j] = prevV;
                s_bp[(t - 1) * KK + j] = (unsigned char)bp;
            }
        }
        eA = eB;
        eB = eC;
        __syncthreads();
        buf ^= 1;
    }

    // log_norm partial: sum of final P over fwd warps
    if (isA) {
        float sp = prevP;
#pragma unroll
        for (int o = 16; o; o >>= 1) sp += __shfl_xor_sync(0xFFFFFFFFu, sp, o);
        if ((tid & 31) == 0) s_red[tid >> 5] = sp;
    }
    __syncthreads();

    // seq_score partials
    float uacc = 0.f;
    for (int tt = tid; tt < TT; tt += 192) {
        if (tt < len) {
            int tg = target[b * TT + tt];
            uacc += emisb[(size_t)tt * KK + tg];
            if (tt >= 1) uacc += trans_g[target[b * TT + tt - 1] * KK + tg];
        }
    }
#pragma unroll
    for (int o = 16; o; o >>= 1) uacc += __shfl_xor_sync(0xFFFFFFFFu, uacc, o);
    if ((tid & 31) == 0) s_red[2 + (tid >> 5)] = uacc;
    __syncthreads();

    if (tid == 0) {
        float sumP = s_red[0] + s_red[1];
        float score = 0.f;
#pragma unroll
        for (int w = 0; w < 6; w++) score += s_red[2 + w];
        const float LN2 = 0.69314718055994531f;
        out_ll[b] = score - ((float)iexp * LN2 + logf(sumP));

        // Viterbi backtrack (first-max tie-break)
        float bvv = s_v[buf][0];
        int tg = 0;
#pragma unroll
        for (int k = 1; k < KK; k++)
            if (s_v[buf][k] > bvv) { bvv = s_v[buf][k]; tg = k; }
        s_path[TT - 1] = tg;
        for (int t = TT - 1; t >= 1; t--) {
            tg = s_bp[(t - 1) * KK + tg];
            s_path[t - 1] = tg;
        }
    }
    __syncthreads();

    for (int tt = tid; tt < TT; tt += 192)
        out_dec[(size_t)b * TT + tt] = (float)((tt < len) ? s_path[tt] : 0);
}

// ---------------------------------------------------------------------------
extern "C" void kernel_launch(void* const* d_in, const int* in_sizes, int n_in,
                              void* d_out, int out_size) {
    const float* hidden = (const float*)d_in[0];
    const int*   masks  = (const int*)d_in[1];
    const int*   target = (const int*)d_in[2];
    const float* Wm     = (const float*)d_in[3];
    const float* bias   = (const float*)d_in[4];
    const float* trans  = (const float*)d_in[5];
    float* out = (float*)d_out;

    gemm_emis_kernel<<<BB * TT / 128, 256>>>(hidden, Wm, bias);
    crf_kernel<<<BB, 192>>>(masks, target, trans, out, out + (size_t)BB * TT);
}